// round 1
// baseline (speedup 1.0000x reference)
#include <cuda_runtime.h>
#include <cstdint>

typedef unsigned long long u64;

// ---- packed f32x2 helpers (sm_103a) ----
__device__ __forceinline__ u64 pack2(float lo, float hi) {
    u64 r;
    asm("mov.b64 %0, {%1, %2};" : "=l"(r) : "f"(lo), "f"(hi));
    return r;
}
__device__ __forceinline__ float2 unpack2(u64 v) {
    float2 f;
    asm("mov.b64 {%0, %1}, %2;" : "=f"(f.x), "=f"(f.y) : "l"(v));
    return f;
}
__device__ __forceinline__ void fma2(u64& d, u64 a, u64 b, u64 c) {
    asm("fma.rn.f32x2 %0, %1, %2, %3;" : "=l"(d) : "l"(a), "l"(b), "l"(c));
}

// ---- fast-but-accurate activations (EX2 + RCP on MUFU) ----
__device__ __forceinline__ float fsig(float x) {
    float e = __expf(-x);
    return __fdividef(1.0f, 1.0f + e);
}
__device__ __forceinline__ float ftanh(float x) {
    float e = __expf(-2.0f * x);
    return __fdividef(2.0f, 1.0f + e) - 1.0f;
}

// 8 threads per sequence. Thread (lane%8)=hid owns hidden unit `hid` of both
// LSTM layers: it computes gate rows {hid, hid+8, hid+16, hid+24} (i,f,g,o in
// PyTorch order), packed pairwise into f32x2 accumulators (i,f) and (g,o).
// Hidden state is exchanged inside the 8-lane group via shuffles.
__global__ void __launch_bounds__(128) lstm_fused(
    const float* __restrict__ input,
    const float* __restrict__ w_ih0, const float* __restrict__ w_hh0,
    const float* __restrict__ b_ih0, const float* __restrict__ b_hh0,
    const float* __restrict__ w_ih1, const float* __restrict__ w_hh1,
    const float* __restrict__ b_ih1, const float* __restrict__ b_hh1,
    const float* __restrict__ w_mlp, const float* __restrict__ b_mlp,
    float* __restrict__ out, int B)
{
    const int T = 256;
    int tid  = blockIdx.x * blockDim.x + threadIdx.x;
    int b    = tid >> 3;
    int hid  = tid & 7;
    int lane = threadIdx.x & 31;
    int gbase = lane & 24;   // first lane of this 8-lane group
    if (b >= B) return;      // warp-uniform for B % 4 == 0

    const int ri = hid, rf = hid + 8, rg = hid + 16, ro = hid + 24;

    // ---- load weights into registers, pre-packed for f32x2 ----
    u64 wih0_if[2], wih0_go[2];
#pragma unroll
    for (int k = 0; k < 2; k++) {
        wih0_if[k] = pack2(w_ih0[ri*2+k], w_ih0[rf*2+k]);
        wih0_go[k] = pack2(w_ih0[rg*2+k], w_ih0[ro*2+k]);
    }
    u64 whh0_if[8], whh0_go[8], wih1_if[8], wih1_go[8], whh1_if[8], whh1_go[8];
#pragma unroll
    for (int k = 0; k < 8; k++) {
        whh0_if[k] = pack2(w_hh0[ri*8+k], w_hh0[rf*8+k]);
        whh0_go[k] = pack2(w_hh0[rg*8+k], w_hh0[ro*8+k]);
        wih1_if[k] = pack2(w_ih1[ri*8+k], w_ih1[rf*8+k]);
        wih1_go[k] = pack2(w_ih1[rg*8+k], w_ih1[ro*8+k]);
        whh1_if[k] = pack2(w_hh1[ri*8+k], w_hh1[rf*8+k]);
        whh1_go[k] = pack2(w_hh1[rg*8+k], w_hh1[ro*8+k]);
    }
    const u64 bias0_if = pack2(b_ih0[ri]+b_hh0[ri], b_ih0[rf]+b_hh0[rf]);
    const u64 bias0_go = pack2(b_ih0[rg]+b_hh0[rg], b_ih0[ro]+b_hh0[ro]);
    const u64 bias1_if = pack2(b_ih1[ri]+b_hh1[ri], b_ih1[rf]+b_hh1[rf]);
    const u64 bias1_go = pack2(b_ih1[rg]+b_hh1[rg], b_ih1[ro]+b_hh1[ro]);

    // input is [B, T, 2] (batch_first); per-sequence base, read as float2
    const float2* xb = reinterpret_cast<const float2*>(input) + (size_t)b * T;
    float2 x = xb[0];

    float c0 = 0.f, h0 = 0.f, c1 = 0.f, h1 = 0.f;

    for (int t = 0; t < T; t++) {
        // ================= layer 0 =================
        u64 aif = bias0_if, ago = bias0_go;
        {
            u64 x0 = pack2(x.x, x.x), x1 = pack2(x.y, x.y);
            fma2(aif, x0, wih0_if[0], aif); fma2(ago, x0, wih0_go[0], ago);
            fma2(aif, x1, wih0_if[1], aif); fma2(ago, x1, wih0_go[1], ago);
        }
#pragma unroll
        for (int k = 0; k < 8; k++) {
            float hk = __shfl_sync(0xffffffffu, h0, gbase + k);
            u64 h2 = pack2(hk, hk);
            fma2(aif, h2, whh0_if[k], aif);
            fma2(ago, h2, whh0_go[k], ago);
        }
        {
            float2 gif = unpack2(aif), ggo = unpack2(ago);
            float ig = fsig(gif.x), fg = fsig(gif.y);
            float gg = ftanh(ggo.x), og = fsig(ggo.y);
            c0 = fg * c0 + ig * gg;
            h0 = og * ftanh(c0);
        }

        // prefetch next x while layer-1 math runs
        int tn = (t < T - 1) ? (t + 1) : t;
        x = xb[tn];

        // ================= layer 1 =================
        aif = bias1_if; ago = bias1_go;
#pragma unroll
        for (int k = 0; k < 8; k++) {
            float ak = __shfl_sync(0xffffffffu, h0, gbase + k);
            u64 a2 = pack2(ak, ak);
            fma2(aif, a2, wih1_if[k], aif);
            fma2(ago, a2, wih1_go[k], ago);
        }
#pragma unroll
        for (int k = 0; k < 8; k++) {
            float bk = __shfl_sync(0xffffffffu, h1, gbase + k);
            u64 b2 = pack2(bk, bk);
            fma2(aif, b2, whh1_if[k], aif);
            fma2(ago, b2, whh1_go[k], ago);
        }
        {
            float2 gif = unpack2(aif), ggo = unpack2(ago);
            float i1 = fsig(gif.x), f1 = fsig(gif.y);
            float g1 = ftanh(ggo.x), o1 = fsig(ggo.y);
            c1 = f1 * c1 + i1 * g1;
            h1 = o1 * ftanh(c1);
        }
    }

    // ================= MLP head: out[b] = h1 @ w_mlp^T + b_mlp =================
    float p0 = h1 * w_mlp[hid];
    float p1 = h1 * w_mlp[8 + hid];
#pragma unroll
    for (int off = 1; off < 8; off <<= 1) {
        p0 += __shfl_xor_sync(0xffffffffu, p0, off);
        p1 += __shfl_xor_sync(0xffffffffu, p1, off);
    }
    if (hid == 0) {
        float2 o;
        o.x = p0 + b_mlp[0];
        o.y = p1 + b_mlp[1];
        reinterpret_cast<float2*>(out)[b] = o;
    }
}

extern "C" void kernel_launch(void* const* d_in, const int* in_sizes, int n_in,
                              void* d_out, int out_size) {
    const float* input = (const float*)d_in[0];
    const float* w_ih0 = (const float*)d_in[1];
    const float* w_hh0 = (const float*)d_in[2];
    const float* b_ih0 = (const float*)d_in[3];
    const float* b_hh0 = (const float*)d_in[4];
    const float* w_ih1 = (const float*)d_in[5];
    const float* w_hh1 = (const float*)d_in[6];
    const float* b_ih1 = (const float*)d_in[7];
    const float* b_hh1 = (const float*)d_in[8];
    const float* w_mlp = (const float*)d_in[9];
    const float* b_mlp = (const float*)d_in[10];

    const int T = 256, IN = 2;
    int B = in_sizes[0] / (T * IN);

    int threads = B * 8;
    int block = 128;
    int grid = (threads + block - 1) / block;

    lstm_fused<<<grid, block>>>(input, w_ih0, w_hh0, b_ih0, b_hh0,
                                w_ih1, w_hh1, b_ih1, b_hh1,
                                w_mlp, b_mlp, (float*)d_out, B);
}

// round 2
// speedup vs baseline: 1.0759x; 1.0759x over previous
#include <cuda_runtime.h>
#include <cstdint>

typedef unsigned long long u64;

// ---- packed f32x2 helpers (sm_103a) ----
__device__ __forceinline__ u64 pack2(float lo, float hi) {
    u64 r;
    asm("mov.b64 %0, {%1, %2};" : "=l"(r) : "f"(lo), "f"(hi));
    return r;
}
__device__ __forceinline__ float2 unpack2(u64 v) {
    float2 f;
    asm("mov.b64 {%0, %1}, %2;" : "=f"(f.x), "=f"(f.y) : "l"(v));
    return f;
}
__device__ __forceinline__ void fma2(u64& d, u64 a, u64 b, u64 c) {
    asm("fma.rn.f32x2 %0, %1, %2, %3;" : "=l"(d) : "l"(a), "l"(b), "l"(c));
}

// ---- fast-but-accurate activations (EX2 + RCP on MUFU) ----
__device__ __forceinline__ float fsig(float x) {
    float e = __expf(-x);
    return __fdividef(1.0f, 1.0f + e);
}
__device__ __forceinline__ float ftanh(float x) {
    float e = __expf(-2.0f * x);
    return __fdividef(2.0f, 1.0f + e) - 1.0f;
}

// 8 threads per sequence-PAIR. Thread (lane%8)=hid owns hidden unit `hid` of
// both LSTM layers for TWO independent sequences (A and B), giving two
// independent dependency chains per thread to hide SHFL/FMA/MUFU latency.
// Gate rows {hid, hid+8, hid+16, hid+24} (i,f,g,o), packed pairwise into
// f32x2 accumulators (i,f) and (g,o). Hidden-state broadcast via shuffles
// within the 8-lane group.
__global__ void __launch_bounds__(128) lstm_fused2(
    const float* __restrict__ input,
    const float* __restrict__ w_ih0, const float* __restrict__ w_hh0,
    const float* __restrict__ b_ih0, const float* __restrict__ b_hh0,
    const float* __restrict__ w_ih1, const float* __restrict__ w_hh1,
    const float* __restrict__ b_ih1, const float* __restrict__ b_hh1,
    const float* __restrict__ w_mlp, const float* __restrict__ b_mlp,
    float* __restrict__ out, int B)
{
    const int T = 256;
    int tid  = blockIdx.x * blockDim.x + threadIdx.x;
    int grp  = tid >> 3;          // sequence-pair index, [0, B/2)
    int hid  = tid & 7;
    int lane = threadIdx.x & 31;
    int gbase = lane & 24;        // first lane of this 8-lane group
    int half = B >> 1;
    if (grp >= half) return;

    int bA = grp;                 // sequence A
    int bB = grp + half;          // sequence B

    const int ri = hid, rf = hid + 8, rg = hid + 16, ro = hid + 24;

    // ---- load weights into registers, pre-packed for f32x2 (shared A/B) ----
    u64 wih0_if[2], wih0_go[2];
#pragma unroll
    for (int k = 0; k < 2; k++) {
        wih0_if[k] = pack2(w_ih0[ri*2+k], w_ih0[rf*2+k]);
        wih0_go[k] = pack2(w_ih0[rg*2+k], w_ih0[ro*2+k]);
    }
    u64 whh0_if[8], whh0_go[8], wih1_if[8], wih1_go[8], whh1_if[8], whh1_go[8];
#pragma unroll
    for (int k = 0; k < 8; k++) {
        whh0_if[k] = pack2(w_hh0[ri*8+k], w_hh0[rf*8+k]);
        whh0_go[k] = pack2(w_hh0[rg*8+k], w_hh0[ro*8+k]);
        wih1_if[k] = pack2(w_ih1[ri*8+k], w_ih1[rf*8+k]);
        wih1_go[k] = pack2(w_ih1[rg*8+k], w_ih1[ro*8+k]);
        whh1_if[k] = pack2(w_hh1[ri*8+k], w_hh1[rf*8+k]);
        whh1_go[k] = pack2(w_hh1[rg*8+k], w_hh1[ro*8+k]);
    }
    const u64 bias0_if = pack2(b_ih0[ri]+b_hh0[ri], b_ih0[rf]+b_hh0[rf]);
    const u64 bias0_go = pack2(b_ih0[rg]+b_hh0[rg], b_ih0[ro]+b_hh0[ro]);
    const u64 bias1_if = pack2(b_ih1[ri]+b_hh1[ri], b_ih1[rf]+b_hh1[rf]);
    const u64 bias1_go = pack2(b_ih1[rg]+b_hh1[rg], b_ih1[ro]+b_hh1[ro]);

    // input is [B, T, 2] (batch_first); per-sequence base, read as float2
    const float2* xbA = reinterpret_cast<const float2*>(input) + (size_t)bA * T;
    const float2* xbB = reinterpret_cast<const float2*>(input) + (size_t)bB * T;
    float2 xA = xbA[0];
    float2 xB = xbB[0];

    float c0A = 0.f, h0A = 0.f, c1A = 0.f, h1A = 0.f;
    float c0B = 0.f, h0B = 0.f, c1B = 0.f, h1B = 0.f;

    for (int t = 0; t < T; t++) {
        // ================= layer 0 (A and B interleaved) =================
        u64 aifA = bias0_if, agoA = bias0_go;
        u64 aifB = bias0_if, agoB = bias0_go;
        {
            u64 x0A = pack2(xA.x, xA.x), x1A = pack2(xA.y, xA.y);
            u64 x0B = pack2(xB.x, xB.x), x1B = pack2(xB.y, xB.y);
            fma2(aifA, x0A, wih0_if[0], aifA); fma2(agoA, x0A, wih0_go[0], agoA);
            fma2(aifB, x0B, wih0_if[0], aifB); fma2(agoB, x0B, wih0_go[0], agoB);
            fma2(aifA, x1A, wih0_if[1], aifA); fma2(agoA, x1A, wih0_go[1], agoA);
            fma2(aifB, x1B, wih0_if[1], aifB); fma2(agoB, x1B, wih0_go[1], agoB);
        }
#pragma unroll
        for (int k = 0; k < 8; k++) {
            float hkA = __shfl_sync(0xffffffffu, h0A, gbase + k);
            float hkB = __shfl_sync(0xffffffffu, h0B, gbase + k);
            u64 h2A = pack2(hkA, hkA);
            u64 h2B = pack2(hkB, hkB);
            fma2(aifA, h2A, whh0_if[k], aifA);
            fma2(agoA, h2A, whh0_go[k], agoA);
            fma2(aifB, h2B, whh0_if[k], aifB);
            fma2(agoB, h2B, whh0_go[k], agoB);
        }
        {
            float2 gifA = unpack2(aifA), ggoA = unpack2(agoA);
            float2 gifB = unpack2(aifB), ggoB = unpack2(agoB);
            float igA = fsig(gifA.x), fgA = fsig(gifA.y);
            float igB = fsig(gifB.x), fgB = fsig(gifB.y);
            float ggA = ftanh(ggoA.x), ogA = fsig(ggoA.y);
            float ggB = ftanh(ggoB.x), ogB = fsig(ggoB.y);
            c0A = fgA * c0A + igA * ggA;
            c0B = fgB * c0B + igB * ggB;
            h0A = ogA * ftanh(c0A);
            h0B = ogB * ftanh(c0B);
        }

        // prefetch next x while layer-1 math runs
        int tn = (t < T - 1) ? (t + 1) : t;
        xA = xbA[tn];
        xB = xbB[tn];

        // ================= layer 1 (A and B interleaved) =================
        aifA = bias1_if; agoA = bias1_go;
        aifB = bias1_if; agoB = bias1_go;
#pragma unroll
        for (int k = 0; k < 8; k++) {
            float akA = __shfl_sync(0xffffffffu, h0A, gbase + k);
            float akB = __shfl_sync(0xffffffffu, h0B, gbase + k);
            u64 a2A = pack2(akA, akA);
            u64 a2B = pack2(akB, akB);
            fma2(aifA, a2A, wih1_if[k], aifA);
            fma2(agoA, a2A, wih1_go[k], agoA);
            fma2(aifB, a2B, wih1_if[k], aifB);
            fma2(agoB, a2B, wih1_go[k], agoB);
        }
#pragma unroll
        for (int k = 0; k < 8; k++) {
            float bkA = __shfl_sync(0xffffffffu, h1A, gbase + k);
            float bkB = __shfl_sync(0xffffffffu, h1B, gbase + k);
            u64 b2A = pack2(bkA, bkA);
            u64 b2B = pack2(bkB, bkB);
            fma2(aifA, b2A, whh1_if[k], aifA);
            fma2(agoA, b2A, whh1_go[k], agoA);
            fma2(aifB, b2B, whh1_if[k], aifB);
            fma2(agoB, b2B, whh1_go[k], agoB);
        }
        {
            float2 gifA = unpack2(aifA), ggoA = unpack2(agoA);
            float2 gifB = unpack2(aifB), ggoB = unpack2(agoB);
            float i1A = fsig(gifA.x), f1A = fsig(gifA.y);
            float i1B = fsig(gifB.x), f1B = fsig(gifB.y);
            float g1A = ftanh(ggoA.x), o1A = fsig(ggoA.y);
            float g1B = ftanh(ggoB.x), o1B = fsig(ggoB.y);
            c1A = f1A * c1A + i1A * g1A;
            c1B = f1B * c1B + i1B * g1B;
            h1A = o1A * ftanh(c1A);
            h1B = o1B * ftanh(c1B);
        }
    }

    // ================= MLP head for both sequences =================
    float p0A = h1A * w_mlp[hid];
    float p1A = h1A * w_mlp[8 + hid];
    float p0B = h1B * w_mlp[hid];
    float p1B = h1B * w_mlp[8 + hid];
#pragma unroll
    for (int off = 1; off < 8; off <<= 1) {
        p0A += __shfl_xor_sync(0xffffffffu, p0A, off);
        p1A += __shfl_xor_sync(0xffffffffu, p1A, off);
        p0B += __shfl_xor_sync(0xffffffffu, p0B, off);
        p1B += __shfl_xor_sync(0xffffffffu, p1B, off);
    }
    if (hid == 0) {
        float2 oA, oB;
        oA.x = p0A + b_mlp[0];
        oA.y = p1A + b_mlp[1];
        oB.x = p0B + b_mlp[0];
        oB.y = p1B + b_mlp[1];
        reinterpret_cast<float2*>(out)[bA] = oA;
        reinterpret_cast<float2*>(out)[bB] = oB;
    }
}

extern "C" void kernel_launch(void* const* d_in, const int* in_sizes, int n_in,
                              void* d_out, int out_size) {
    const float* input = (const float*)d_in[0];
    const float* w_ih0 = (const float*)d_in[1];
    const float* w_hh0 = (const float*)d_in[2];
    const float* b_ih0 = (const float*)d_in[3];
    const float* b_hh0 = (const float*)d_in[4];
    const float* w_ih1 = (const float*)d_in[5];
    const float* w_hh1 = (const float*)d_in[6];
    const float* b_ih1 = (const float*)d_in[7];
    const float* b_hh1 = (const float*)d_in[8];
    const float* w_mlp = (const float*)d_in[9];
    const float* b_mlp = (const float*)d_in[10];

    const int T = 256, IN = 2;
    int B = in_sizes[0] / (T * IN);

    int threads = (B >> 1) * 8;     // 8 threads per sequence-pair
    int block = 128;
    int grid = (threads + block - 1) / block;

    lstm_fused2<<<grid, block>>>(input, w_ih0, w_hh0, b_ih0, b_hh0,
                                 w_ih1, w_hh1, b_ih1, b_hh1,
                                 w_mlp, b_mlp, (float*)d_out, B);
}

// round 3
// speedup vs baseline: 1.4221x; 1.3217x over previous
#include <cuda_runtime.h>
#include <cstdint>

typedef unsigned long long u64;

// ---- packed f32x2 helpers (sm_103a) ----
__device__ __forceinline__ u64 pack2(float lo, float hi) {
    u64 r;
    asm("mov.b64 %0, {%1, %2};" : "=l"(r) : "f"(lo), "f"(hi));
    return r;
}
__device__ __forceinline__ float2 unpack2(u64 v) {
    float2 f;
    asm("mov.b64 {%0, %1}, %2;" : "=f"(f.x), "=f"(f.y) : "l"(v));
    return f;
}
__device__ __forceinline__ void fma2(u64& d, u64 a, u64 b, u64 c) {
    asm("fma.rn.f32x2 %0, %1, %2, %3;" : "=l"(d) : "l"(a), "l"(b), "l"(c));
}
__device__ __forceinline__ void add2(u64& d, u64 a, u64 b) {
    asm("add.rn.f32x2 %0, %1, %2;" : "=l"(d) : "l"(a), "l"(b));
}

// ---- single-instruction tanh (MUFU.TANH, sm_75+) ----
__device__ __forceinline__ float tanha(float x) {
    float r;
    asm("tanh.approx.f32 %0, %1;" : "=f"(r) : "f"(x));
    return r;
}
// sigmoid(z) = 0.5*tanh(z/2) + 0.5 ; the /2 is pre-folded into the weights,
// so the caller passes z/2 and this is just MUFU.TANH + FFMA.
__device__ __forceinline__ float sig_prescaled(float half_z) {
    return fmaf(tanha(half_z), 0.5f, 0.5f);
}

// 8 threads per sequence-PAIR; thread (lane%8)=hid owns hidden unit `hid` of
// both layers for TWO sequences (A,B). Gate rows {hid,hid+8,hid+16,hid+24}
// (i,f,g,o) packed into f32x2 accumulators (i,f) and (g,o). Sigmoid gate rows
// (i,f,o) are pre-scaled by 0.5 at weight-load so sigmoid = TANH+FFMA.
// Accumulation chains are split into independent halves to shorten the
// per-step critical path.
__global__ void __launch_bounds__(128) lstm_fused3(
    const float* __restrict__ input,
    const float* __restrict__ w_ih0, const float* __restrict__ w_hh0,
    const float* __restrict__ b_ih0, const float* __restrict__ b_hh0,
    const float* __restrict__ w_ih1, const float* __restrict__ w_hh1,
    const float* __restrict__ b_ih1, const float* __restrict__ b_hh1,
    const float* __restrict__ w_mlp, const float* __restrict__ b_mlp,
    float* __restrict__ out, int B)
{
    const int T = 256;
    int tid  = blockIdx.x * blockDim.x + threadIdx.x;
    int grp  = tid >> 3;
    int hid  = tid & 7;
    int lane = threadIdx.x & 31;
    int gbase = lane & 24;
    int half = B >> 1;
    if (grp >= half) return;

    int bA = grp;
    int bB = grp + half;

    const int ri = hid, rf = hid + 8, rg = hid + 16, ro = hid + 24;

    // ---- weights in registers, f32x2-packed; i,f,o rows pre-scaled by 0.5 ----
    u64 wih0_if[2], wih0_go[2];
#pragma unroll
    for (int k = 0; k < 2; k++) {
        wih0_if[k] = pack2(0.5f*w_ih0[ri*2+k], 0.5f*w_ih0[rf*2+k]);
        wih0_go[k] = pack2(      w_ih0[rg*2+k], 0.5f*w_ih0[ro*2+k]);
    }
    u64 whh0_if[8], whh0_go[8], wih1_if[8], wih1_go[8], whh1_if[8], whh1_go[8];
#pragma unroll
    for (int k = 0; k < 8; k++) {
        whh0_if[k] = pack2(0.5f*w_hh0[ri*8+k], 0.5f*w_hh0[rf*8+k]);
        whh0_go[k] = pack2(      w_hh0[rg*8+k], 0.5f*w_hh0[ro*8+k]);
        wih1_if[k] = pack2(0.5f*w_ih1[ri*8+k], 0.5f*w_ih1[rf*8+k]);
        wih1_go[k] = pack2(      w_ih1[rg*8+k], 0.5f*w_ih1[ro*8+k]);
        whh1_if[k] = pack2(0.5f*w_hh1[ri*8+k], 0.5f*w_hh1[rf*8+k]);
        whh1_go[k] = pack2(      w_hh1[rg*8+k], 0.5f*w_hh1[ro*8+k]);
    }
    const u64 bias0_if = pack2(0.5f*(b_ih0[ri]+b_hh0[ri]), 0.5f*(b_ih0[rf]+b_hh0[rf]));
    const u64 bias0_go = pack2(      b_ih0[rg]+b_hh0[rg] , 0.5f*(b_ih0[ro]+b_hh0[ro]));
    const u64 bias1_if = pack2(0.5f*(b_ih1[ri]+b_hh1[ri]), 0.5f*(b_ih1[rf]+b_hh1[rf]));
    const u64 bias1_go = pack2(      b_ih1[rg]+b_hh1[rg] , 0.5f*(b_ih1[ro]+b_hh1[ro]));

    const float2* xbA = reinterpret_cast<const float2*>(input) + (size_t)bA * T;
    const float2* xbB = reinterpret_cast<const float2*>(input) + (size_t)bB * T;
    float2 xA = xbA[0];
    float2 xB = xbB[0];

    float c0A = 0.f, h0A = 0.f, c1A = 0.f, h1A = 0.f;
    float c0B = 0.f, h0B = 0.f, c1B = 0.f, h1B = 0.f;

    for (int t = 0; t < T; t++) {
        // ================= layer 0 (A,B interleaved; split chains) ==========
        u64 aifA = bias0_if, agoA = bias0_go;   // chain 0: bias + x + k<4
        u64 aifB = bias0_if, agoB = bias0_go;
        u64 bifA = 0, bgoA = 0, bifB = 0, bgoB = 0;  // chain 1: k>=4
        {
            u64 x0A = pack2(xA.x, xA.x), x1A = pack2(xA.y, xA.y);
            u64 x0B = pack2(xB.x, xB.x), x1B = pack2(xB.y, xB.y);
            fma2(aifA, x0A, wih0_if[0], aifA); fma2(agoA, x0A, wih0_go[0], agoA);
            fma2(aifB, x0B, wih0_if[0], aifB); fma2(agoB, x0B, wih0_go[0], agoB);
            fma2(aifA, x1A, wih0_if[1], aifA); fma2(agoA, x1A, wih0_go[1], agoA);
            fma2(aifB, x1B, wih0_if[1], aifB); fma2(agoB, x1B, wih0_go[1], agoB);
        }
#pragma unroll
        for (int k = 0; k < 4; k++) {
            float hkA = __shfl_sync(0xffffffffu, h0A, gbase + k);
            float hkB = __shfl_sync(0xffffffffu, h0B, gbase + k);
            u64 h2A = pack2(hkA, hkA), h2B = pack2(hkB, hkB);
            fma2(aifA, h2A, whh0_if[k], aifA); fma2(agoA, h2A, whh0_go[k], agoA);
            fma2(aifB, h2B, whh0_if[k], aifB); fma2(agoB, h2B, whh0_go[k], agoB);
        }
#pragma unroll
        for (int k = 4; k < 8; k++) {
            float hkA = __shfl_sync(0xffffffffu, h0A, gbase + k);
            float hkB = __shfl_sync(0xffffffffu, h0B, gbase + k);
            u64 h2A = pack2(hkA, hkA), h2B = pack2(hkB, hkB);
            fma2(bifA, h2A, whh0_if[k], bifA); fma2(bgoA, h2A, whh0_go[k], bgoA);
            fma2(bifB, h2B, whh0_if[k], bifB); fma2(bgoB, h2B, whh0_go[k], bgoB);
        }
        add2(aifA, aifA, bifA); add2(agoA, agoA, bgoA);
        add2(aifB, aifB, bifB); add2(agoB, agoB, bgoB);
        {
            float2 gifA = unpack2(aifA), ggoA = unpack2(agoA);
            float2 gifB = unpack2(aifB), ggoB = unpack2(agoB);
            float igA = sig_prescaled(gifA.x), fgA = sig_prescaled(gifA.y);
            float igB = sig_prescaled(gifB.x), fgB = sig_prescaled(gifB.y);
            float ggA = tanha(ggoA.x), ogA = sig_prescaled(ggoA.y);
            float ggB = tanha(ggoB.x), ogB = sig_prescaled(ggoB.y);
            c0A = fgA * c0A + igA * ggA;
            c0B = fgB * c0B + igB * ggB;
            h0A = ogA * tanha(c0A);
            h0B = ogB * tanha(c0B);
        }

        int tn = (t < T - 1) ? (t + 1) : t;
        xA = xbA[tn];
        xB = xbB[tn];

        // ================= layer 1 (split: h0-loop vs h1-loop chains) =======
        aifA = bias1_if; agoA = bias1_go;
        aifB = bias1_if; agoB = bias1_go;
        bifA = 0; bgoA = 0; bifB = 0; bgoB = 0;
#pragma unroll
        for (int k = 0; k < 8; k++) {
            float akA = __shfl_sync(0xffffffffu, h0A, gbase + k);
            float akB = __shfl_sync(0xffffffffu, h0B, gbase + k);
            u64 a2A = pack2(akA, akA), a2B = pack2(akB, akB);
            fma2(aifA, a2A, wih1_if[k], aifA); fma2(agoA, a2A, wih1_go[k], agoA);
            fma2(aifB, a2B, wih1_if[k], aifB); fma2(agoB, a2B, wih1_go[k], agoB);
        }
#pragma unroll
        for (int k = 0; k < 8; k++) {
            float bkA = __shfl_sync(0xffffffffu, h1A, gbase + k);
            float bkB = __shfl_sync(0xffffffffu, h1B, gbase + k);
            u64 b2A = pack2(bkA, bkA), b2B = pack2(bkB, bkB);
            fma2(bifA, b2A, whh1_if[k], bifA); fma2(bgoA, b2A, whh1_go[k], bgoA);
            fma2(bifB, b2B, whh1_if[k], bifB); fma2(bgoB, b2B, whh1_go[k], bgoB);
        }
        add2(aifA, aifA, bifA); add2(agoA, agoA, bgoA);
        add2(aifB, aifB, bifB); add2(agoB, agoB, bgoB);
        {
            float2 gifA = unpack2(aifA), ggoA = unpack2(agoA);
            float2 gifB = unpack2(aifB), ggoB = unpack2(agoB);
            float i1A = sig_prescaled(gifA.x), f1A = sig_prescaled(gifA.y);
            float i1B = sig_prescaled(gifB.x), f1B = sig_prescaled(gifB.y);
            float g1A = tanha(ggoA.x), o1A = sig_prescaled(ggoA.y);
            float g1B = tanha(ggoB.x), o1B = sig_prescaled(ggoB.y);
            c1A = f1A * c1A + i1A * g1A;
            c1B = f1B * c1B + i1B * g1B;
            h1A = o1A * tanha(c1A);
            h1B = o1B * tanha(c1B);
        }
    }

    // ================= MLP head =================
    float p0A = h1A * w_mlp[hid];
    float p1A = h1A * w_mlp[8 + hid];
    float p0B = h1B * w_mlp[hid];
    float p1B = h1B * w_mlp[8 + hid];
#pragma unroll
    for (int off = 1; off < 8; off <<= 1) {
        p0A += __shfl_xor_sync(0xffffffffu, p0A, off);
        p1A += __shfl_xor_sync(0xffffffffu, p1A, off);
        p0B += __shfl_xor_sync(0xffffffffu, p0B, off);
        p1B += __shfl_xor_sync(0xffffffffu, p1B, off);
    }
    if (hid == 0) {
        float2 oA, oB;
        oA.x = p0A + b_mlp[0];
        oA.y = p1A + b_mlp[1];
        oB.x = p0B + b_mlp[0];
        oB.y = p1B + b_mlp[1];
        reinterpret_cast<float2*>(out)[bA] = oA;
        reinterpret_cast<float2*>(out)[bB] = oB;
    }
}

extern "C" void kernel_launch(void* const* d_in, const int* in_sizes, int n_in,
                              void* d_out, int out_size) {
    const float* input = (const float*)d_in[0];
    const float* w_ih0 = (const float*)d_in[1];
    const float* w_hh0 = (const float*)d_in[2];
    const float* b_ih0 = (const float*)d_in[3];
    const float* b_hh0 = (const float*)d_in[4];
    const float* w_ih1 = (const float*)d_in[5];
    const float* w_hh1 = (const float*)d_in[6];
    const float* b_ih1 = (const float*)d_in[7];
    const float* b_hh1 = (const float*)d_in[8];
    const float* w_mlp = (const float*)d_in[9];
    const float* b_mlp = (const float*)d_in[10];

    const int T = 256, IN = 2;
    int B = in_sizes[0] / (T * IN);

    int threads = (B >> 1) * 8;
    int block = 128;
    int grid = (threads + block - 1) / block;

    lstm_fused3<<<grid, block>>>(input, w_ih0, w_hh0, b_ih0, b_hh0,
                                 w_ih1, w_hh1, b_ih1, b_hh1,
                                 w_mlp, b_mlp, (float*)d_out, B);
}